// round 2
// baseline (speedup 1.0000x reference)
#include <cuda_runtime.h>
#include <math.h>

#define LD 68

__device__ float g_q[2048 * 2048];
__device__ float g_k[2048 * 512];
__device__ float g_v[2048 * 512];
__device__ float g_ql[2 * 32 * 1024 * 64];
__device__ float g_kl[2 * 8 * 1024 * 64];
__device__ float g_gl[2 * 8 * 1024 * 64];
__device__ float g_vh[2 * 8 * 1024 * 64];
__device__ float g_uw[2 * 8 * 16 * 64 * 128];
__device__ float g_up[2 * 8 * 16 * 64 * 64];
__device__ float g_Spre[2 * 8 * 16 * 64 * 64];
__device__ float g_olin[2048 * 2048];
__device__ float g_omix[2048 * 2048];

// ---------------- 128x128x8 SGEMM: C[MxN] = A[MxK] @ B[KxN], row-major ----------------
__global__ __launch_bounds__(256) void sgemm_kernel(
    const float* __restrict__ A, const float* __restrict__ B,
    float* __restrict__ C, int N, int K) {
  __shared__ float As[8][128];
  __shared__ float Bs[8][128];
  const int tid = threadIdx.x;
  const int tx = tid & 15, ty = tid >> 4;
  const int arow = tid >> 1, acol = (tid & 1) << 2;
  const int brow = tid >> 5, bcol = (tid & 31) << 2;
  const float* Ap = A + (size_t)(blockIdx.y * 128 + arow) * K + acol;
  const float* Bp = B + (size_t)brow * N + blockIdx.x * 128 + bcol;
  float acc[8][8];
#pragma unroll
  for (int i = 0; i < 8; i++)
#pragma unroll
    for (int j = 0; j < 8; j++) acc[i][j] = 0.f;
  for (int k0 = 0; k0 < K; k0 += 8) {
    float4 av = *(const float4*)Ap;
    float4 bv = *(const float4*)Bp;
    As[acol + 0][arow] = av.x;
    As[acol + 1][arow] = av.y;
    As[acol + 2][arow] = av.z;
    As[acol + 3][arow] = av.w;
    *(float4*)&Bs[brow][bcol] = bv;
    __syncthreads();
#pragma unroll
    for (int kk = 0; kk < 8; kk++) {
      float a[8], b[8];
      *(float4*)&a[0] = *(const float4*)&As[kk][ty * 8];
      *(float4*)&a[4] = *(const float4*)&As[kk][ty * 8 + 4];
      *(float4*)&b[0] = *(const float4*)&Bs[kk][tx * 8];
      *(float4*)&b[4] = *(const float4*)&Bs[kk][tx * 8 + 4];
#pragma unroll
      for (int i = 0; i < 8; i++)
#pragma unroll
        for (int j = 0; j < 8; j++) acc[i][j] += a[i] * b[j];
    }
    __syncthreads();
    Ap += 8;
    Bp += (size_t)8 * N;
  }
  float* Cp = C + (size_t)(blockIdx.y * 128 + ty * 8) * N + blockIdx.x * 128 + tx * 8;
#pragma unroll
  for (int i = 0; i < 8; i++) {
    *(float4*)&Cp[(size_t)i * N] = make_float4(acc[i][0], acc[i][1], acc[i][2], acc[i][3]);
    *(float4*)&Cp[(size_t)i * N + 4] = make_float4(acc[i][4], acc[i][5], acc[i][6], acc[i][7]);
  }
}

// ---------------- feature maps: softmax(q), softmax(k), logsigmoid(k)/16, v split ----------------
__global__ __launch_bounds__(256) void prep_kernel() {
  int gw = (blockIdx.x * 256 + threadIdx.x) >> 5;
  int lane = threadIdx.x & 31;
  if (gw < 65536) {
    int token = gw >> 5, h = gw & 31;
    const float* src = g_q + (size_t)token * 2048 + h * 64;
    float x0 = src[lane], x1 = src[lane + 32];
    float mx = fmaxf(x0, x1);
#pragma unroll
    for (int o = 16; o > 0; o >>= 1) mx = fmaxf(mx, __shfl_xor_sync(0xffffffffu, mx, o));
    float e0 = __expf(x0 - mx), e1 = __expf(x1 - mx);
    float s = e0 + e1;
#pragma unroll
    for (int o = 16; o > 0; o >>= 1) s += __shfl_xor_sync(0xffffffffu, s, o);
    float inv = 1.f / s;
    int b = token >> 10, n = token & 1023;
    float* dst = g_ql + ((size_t)((b * 32 + h) * 1024 + n)) * 64;
    dst[lane] = e0 * inv;
    dst[lane + 32] = e1 * inv;
  } else {
    int j = gw - 65536;
    int token = j >> 3, hk = j & 7;
    const float* ks = g_k + (size_t)token * 512 + hk * 64;
    const float* vs = g_v + (size_t)token * 512 + hk * 64;
    float x0 = ks[lane], x1 = ks[lane + 32];
    float mx = fmaxf(x0, x1);
#pragma unroll
    for (int o = 16; o > 0; o >>= 1) mx = fmaxf(mx, __shfl_xor_sync(0xffffffffu, mx, o));
    float e0 = __expf(x0 - mx), e1 = __expf(x1 - mx);
    float s = e0 + e1;
#pragma unroll
    for (int o = 16; o > 0; o >>= 1) s += __shfl_xor_sync(0xffffffffu, s, o);
    float inv = 1.f / s;
    int b = token >> 10, n = token & 1023;
    size_t base = ((size_t)((b * 8 + hk) * 1024 + n)) * 64;
    g_kl[base + lane] = e0 * inv;
    g_kl[base + lane + 32] = e1 * inv;
    g_gl[base + lane] = (fminf(x0, 0.f) - log1pf(__expf(-fabsf(x0)))) * 0.0625f;
    g_gl[base + lane + 32] = (fminf(x1, 0.f) - log1pf(__expf(-fabsf(x1)))) * 0.0625f;
    g_vh[base + lane] = vs[lane];
    g_vh[base + lane + 32] = vs[lane + 32];
  }
}

// ---------------- per-chunk u,w via forward substitution (chunk-parallel) ----------------
__global__ __launch_bounds__(256) void uw_kernel() {
  extern __shared__ float sm_uw[];
  float* kcT = sm_uw;
  float* kb = kcT + 64 * LD;
  float* L = kb + 64 * LD;
  float* uw = L + 64 * LD;  // [64][136]
  const int bx = blockIdx.x;
  const int g = bx >> 4, ch = bx & 15;
  const int tid = threadIdx.x, tx = tid & 15, ty = tid >> 4;
  size_t base = ((size_t)g * 1024 + ch * 64) * 64;
  for (int idx = tid; idx < 4096; idx += 256) {
    int r = idx >> 6, c = idx & 63;
    float kv = g_kl[base + idx];
    float gv = g_gl[base + idx];
    float vv = g_vh[base + idx];
    kcT[c * LD + r] = kv;
    float kbv = kv * gv;
    kb[r * LD + c] = kbv;
    uw[r * 136 + c] = vv * gv;
    uw[r * 136 + 64 + c] = kbv;
  }
  __syncthreads();
  float acc[4][4] = {};
#pragma unroll 8
  for (int d = 0; d < 64; d++) {
    float a[4];
#pragma unroll
    for (int i = 0; i < 4; i++) a[i] = kb[(ty * 4 + i) * LD + d];
    float4 b4 = *(const float4*)&kcT[d * LD + tx * 4];
#pragma unroll
    for (int i = 0; i < 4; i++) {
      acc[i][0] += a[i] * b4.x; acc[i][1] += a[i] * b4.y;
      acc[i][2] += a[i] * b4.z; acc[i][3] += a[i] * b4.w;
    }
  }
#pragma unroll
  for (int i = 0; i < 4; i++)
#pragma unroll
    for (int j = 0; j < 4; j++) {
      int ii = ty * 4 + i, jj = tx * 4 + j;
      L[ii * LD + jj] = (ii > jj) ? acc[i][j] : 0.f;
    }
  __syncthreads();
  for (int i = 1; i < 64; i++) {
    if (tid < 128) {
      float s = 0.f;
      const float* Li = L + i * LD;
      for (int j = 0; j < i; j++) s += Li[j] * uw[j * 136 + tid];
      uw[i * 136 + tid] -= s;
    }
    __syncthreads();
  }
  float* dst = g_uw + (size_t)bx * 8192;
  for (int idx = tid; idx < 8192; idx += 256)
    dst[idx] = uw[(idx >> 7) * 136 + (idx & 127)];
}

// ---------------- sequential state recurrence, one block per (b,hkv) ----------------
__global__ __launch_bounds__(256) void recur_kernel() {
  extern __shared__ float sm_rc[];
  float* S = sm_rc;
  float* w = S + 64 * LD;
  float* up = w + 64 * LD;
  float* kc = up + 64 * LD;
  const int g = blockIdx.x;
  const int tid = threadIdx.x, tx = tid & 15, ty = tid >> 4;
  for (int idx = tid; idx < 4096; idx += 256) S[(idx >> 6) * LD + (idx & 63)] = 0.f;
  __syncthreads();
  for (int ch = 0; ch < 16; ch++) {
    size_t bi = (size_t)(g * 16 + ch);
    const float* uwp = g_uw + bi * 8192;
    size_t kbase = ((size_t)g * 1024 + ch * 64) * 64;
    for (int idx = tid; idx < 4096; idx += 256) {
      int r = idx >> 6, c = idx & 63;
      w[r * LD + c] = uwp[r * 128 + 64 + c];
      kc[r * LD + c] = g_kl[kbase + idx];
      g_Spre[bi * 4096 + idx] = S[r * LD + c];
    }
    __syncthreads();
    float acc[4][4] = {};
#pragma unroll 8
    for (int d = 0; d < 64; d++) {
      float a[4];
#pragma unroll
      for (int i = 0; i < 4; i++) a[i] = w[(ty * 4 + i) * LD + d];
      float4 b4 = *(const float4*)&S[d * LD + tx * 4];
#pragma unroll
      for (int i = 0; i < 4; i++) {
        acc[i][0] += a[i] * b4.x; acc[i][1] += a[i] * b4.y;
        acc[i][2] += a[i] * b4.z; acc[i][3] += a[i] * b4.w;
      }
    }
#pragma unroll
    for (int i = 0; i < 4; i++)
#pragma unroll
      for (int j = 0; j < 4; j++) {
        int r = ty * 4 + i, c = tx * 4 + j;
        float upv = uwp[r * 128 + c] - acc[i][j];
        up[r * LD + c] = upv;
        g_up[bi * 4096 + r * 64 + c] = upv;
      }
    __syncthreads();
    float acc2[4][4] = {};
#pragma unroll 8
    for (int c0 = 0; c0 < 64; c0++) {
      float a[4];
#pragma unroll
      for (int i = 0; i < 4; i++) a[i] = kc[c0 * LD + ty * 4 + i];
      float4 b4 = *(const float4*)&up[c0 * LD + tx * 4];
#pragma unroll
      for (int i = 0; i < 4; i++) {
        acc2[i][0] += a[i] * b4.x; acc2[i][1] += a[i] * b4.y;
        acc2[i][2] += a[i] * b4.z; acc2[i][3] += a[i] * b4.w;
      }
    }
#pragma unroll
    for (int i = 0; i < 4; i++)
#pragma unroll
      for (int j = 0; j < 4; j++)
        S[(ty * 4 + i) * LD + tx * 4 + j] += acc2[i][j];
    __syncthreads();
  }
}

// ---------------- linear-branch output (fully parallel: 1024 blocks) ----------------
__global__ __launch_bounds__(256) void olin_kernel() {
  extern __shared__ float sm_ol[];
  float* QT = sm_ol;
  float* KT = QT + 64 * LD;
  float* S = KT + 64 * LD;
  float* UP = S + 64 * LD;
  float* AT = UP + 64 * LD;
  const int bx = blockIdx.x;
  const int bh = bx >> 4, ch = bx & 15;
  const int b = bh >> 5, h = bh & 31;
  const int g = b * 8 + (h >> 2);
  const int tid = threadIdx.x, tx = tid & 15, ty = tid >> 4;
  size_t qbase = ((size_t)bh * 1024 + ch * 64) * 64;
  size_t kbase = ((size_t)g * 1024 + ch * 64) * 64;
  size_t sbase = (size_t)(g * 16 + ch) * 4096;
  for (int idx = tid; idx < 4096; idx += 256) {
    int r = idx >> 6, c = idx & 63;
    QT[c * LD + r] = g_ql[qbase + idx];
    KT[c * LD + r] = g_kl[kbase + idx];
    S[r * LD + c] = g_Spre[sbase + idx];
    UP[r * LD + c] = g_up[sbase + idx];
  }
  __syncthreads();
  float acc[4][4] = {};
#pragma unroll 8
  for (int d = 0; d < 64; d++) {
    float a[4];
#pragma unroll
    for (int i = 0; i < 4; i++) a[i] = QT[d * LD + ty * 4 + i];
    float4 b4 = *(const float4*)&KT[d * LD + tx * 4];
#pragma unroll
    for (int i = 0; i < 4; i++) {
      acc[i][0] += a[i] * b4.x; acc[i][1] += a[i] * b4.y;
      acc[i][2] += a[i] * b4.z; acc[i][3] += a[i] * b4.w;
    }
  }
#pragma unroll
  for (int i = 0; i < 4; i++)
#pragma unroll
    for (int j = 0; j < 4; j++) {
      int ii = ty * 4 + i, jj = tx * 4 + j;
      AT[ii * LD + jj] = (jj <= ii) ? acc[i][j] : 0.f;
    }
  __syncthreads();
  float o[4][4] = {};
#pragma unroll 8
  for (int d = 0; d < 64; d++) {
    float a[4];
#pragma unroll
    for (int i = 0; i < 4; i++) a[i] = QT[d * LD + ty * 4 + i];
    float4 b4 = *(const float4*)&S[d * LD + tx * 4];
#pragma unroll
    for (int i = 0; i < 4; i++) {
      o[i][0] += a[i] * b4.x; o[i][1] += a[i] * b4.y;
      o[i][2] += a[i] * b4.z; o[i][3] += a[i] * b4.w;
    }
  }
#pragma unroll 8
  for (int j0 = 0; j0 < 64; j0++) {
    float a[4];
#pragma unroll
    for (int i = 0; i < 4; i++) a[i] = AT[(ty * 4 + i) * LD + j0];
    float4 b4 = *(const float4*)&UP[j0 * LD + tx * 4];
#pragma unroll
    for (int i = 0; i < 4; i++) {
      o[i][0] += a[i] * b4.x; o[i][1] += a[i] * b4.y;
      o[i][2] += a[i] * b4.z; o[i][3] += a[i] * b4.w;
    }
  }
#pragma unroll
  for (int i = 0; i < 4; i++) {
    size_t ob = ((size_t)(b * 1024 + ch * 64 + ty * 4 + i)) * 2048 + h * 64 + tx * 4;
    *(float4*)&g_olin[ob] = make_float4(o[i][0], o[i][1], o[i][2], o[i][3]);
  }
}

// ---------------- base causal attention: attn_weights + fused 0.5*(olin+obase) ----------------
__global__ __launch_bounds__(256) void attn_kernel(float* __restrict__ attn_out, int write_attn) {
  extern __shared__ float sm_at[];
  float* QT = sm_at;
  float* KT = QT + 64 * LD;
  float* VS = KT + 64 * LD;
  float* PS = VS + 64 * LD;
  const int qt = blockIdx.x, h = blockIdx.y, b = blockIdx.z;
  const int hk = h >> 2;
  const int tid = threadIdx.x, tx = tid & 15, ty = tid >> 4;
  const int r0 = ty * 4;
  for (int idx = tid; idx < 4096; idx += 256) {
    int r = idx >> 6, d = idx & 63;
    QT[d * LD + r] = g_q[((size_t)(b * 1024 + qt * 64 + r)) * 2048 + h * 64 + d] * 0.125f;
  }
  float m[4], l[4], o[4][4];
#pragma unroll
  for (int i = 0; i < 4; i++) {
    m[i] = -1e30f; l[i] = 0.f;
#pragma unroll
    for (int j = 0; j < 4; j++) o[i][j] = 0.f;
  }
  for (int kt = 0; kt <= qt; kt++) {
    __syncthreads();
    for (int idx = tid; idx < 4096; idx += 256) {
      int r = idx >> 6, d = idx & 63;
      KT[d * LD + r] = g_k[((size_t)(b * 1024 + kt * 64 + r)) * 512 + hk * 64 + d];
    }
    __syncthreads();
    float s[4][4] = {};
#pragma unroll 8
    for (int d = 0; d < 64; d++) {
      float a[4];
#pragma unroll
      for (int i = 0; i < 4; i++) a[i] = QT[d * LD + r0 + i];
      float4 b4 = *(const float4*)&KT[d * LD + tx * 4];
#pragma unroll
      for (int i = 0; i < 4; i++) {
        s[i][0] += a[i] * b4.x; s[i][1] += a[i] * b4.y;
        s[i][2] += a[i] * b4.z; s[i][3] += a[i] * b4.w;
      }
    }
    bool diag = (kt == qt);
#pragma unroll
    for (int i = 0; i < 4; i++) {
      if (diag) {
#pragma unroll
        for (int j = 0; j < 4; j++)
          if (tx * 4 + j > r0 + i) s[i][j] = -1e30f;
      }
      float tmax = fmaxf(fmaxf(s[i][0], s[i][1]), fmaxf(s[i][2], s[i][3]));
#pragma unroll
      for (int off = 8; off > 0; off >>= 1)
        tmax = fmaxf(tmax, __shfl_xor_sync(0xffffffffu, tmax, off));
      float mn = fmaxf(m[i], tmax);
      float ps = __expf(s[i][0] - mn) + __expf(s[i][1] - mn) +
                 __expf(s[i][2] - mn) + __expf(s[i][3] - mn);
#pragma unroll
      for (int off = 8; off > 0; off >>= 1) ps += __shfl_xor_sync(0xffffffffu, ps, off);
      l[i] = l[i] * __expf(m[i] - mn) + ps;
      m[i] = mn;
    }
  }
  float invl[4];
#pragma unroll
  for (int i = 0; i < 4; i++) invl[i] = 1.f / l[i];
  const size_t arow0 = (size_t)(b * 32 + h) * 1024 + (size_t)qt * 64;
  for (int kt = 0; kt < 16; kt++) {
    if (kt <= qt) {
      __syncthreads();
      for (int idx = tid; idx < 4096; idx += 256) {
        int r = idx >> 6, d = idx & 63;
        size_t src = ((size_t)(b * 1024 + kt * 64 + r)) * 512 + hk * 64 + d;
        KT[d * LD + r] = g_k[src];
        VS[r * LD + d] = g_v[src];
      }
      __syncthreads();
      float s[4][4] = {};
#pragma unroll 8
      for (int d = 0; d < 64; d++) {
        float a[4];
#pragma unroll
        for (int i = 0; i < 4; i++) a[i] = QT[d * LD + r0 + i];
        float4 b4 = *(const float4*)&KT[d * LD + tx * 4];
#pragma unroll
        for (int i = 0; i < 4; i++) {
          s[i][0] += a[i] * b4.x; s[i][1] += a[i] * b4.y;
          s[i][2] += a[i] * b4.z; s[i][3] += a[i] * b4.w;
        }
      }
      bool diag = (kt == qt);
#pragma unroll
      for (int i = 0; i < 4; i++) {
        float p[4];
#pragma unroll
        for (int j = 0; j < 4; j++) {
          bool valid = !diag || (tx * 4 + j <= r0 + i);
          p[j] = valid ? __expf(s[i][j] - m[i]) * invl[i] : 0.f;
          PS[(r0 + i) * LD + tx * 4 + j] = p[j];
        }
        if (write_attn) {
          *(float4*)&attn_out[(arow0 + r0 + i) * 1024 + kt * 64 + tx * 4] =
              make_float4(p[0], p[1], p[2], p[3]);
        }
      }
      __syncthreads();
#pragma unroll 8
      for (int j0 = 0; j0 < 64; j0++) {
        float a[4];
#pragma unroll
        for (int i = 0; i < 4; i++) a[i] = PS[(r0 + i) * LD + j0];
        float4 b4 = *(const float4*)&VS[j0 * LD + tx * 4];
#pragma unroll
        for (int i = 0; i < 4; i++) {
          o[i][0] += a[i] * b4.x; o[i][1] += a[i] * b4.y;
          o[i][2] += a[i] * b4.z; o[i][3] += a[i] * b4.w;
        }
      }
    } else if (write_attn) {
#pragma unroll
      for (int i = 0; i < 4; i++)
        *(float4*)&attn_out[(arow0 + r0 + i) * 1024 + kt * 64 + tx * 4] =
            make_float4(0.f, 0.f, 0.f, 0.f);
    }
  }
#pragma unroll
  for (int i = 0; i < 4; i++) {
    size_t ob = ((size_t)(b * 1024 + qt * 64 + r0 + i)) * 2048 + h * 64 + tx * 4;
    float4 ol = *(const float4*)&g_olin[ob];
    *(float4*)&g_omix[ob] = make_float4(0.5f * (ol.x + o[i][0]), 0.5f * (ol.y + o[i][1]),
                                        0.5f * (ol.z + o[i][2]), 0.5f * (ol.w + o[i][3]));
  }
}

extern "C" void kernel_launch(void* const* d_in, const int* in_sizes, int n_in,
                              void* d_out, int out_size) {
  const float* hidden = (const float*)d_in[0];
  const float* Wq = (const float*)d_in[1];
  const float* Wk = (const float*)d_in[2];
  const float* Wv = (const float*)d_in[3];
  const float* Wo = (const float*)d_in[4];
  float* out = (float*)d_out;
  float* attn_out = out + 4194304;
  int write_attn = (out_size >= 71303168) ? 1 : 0;

  float* gq;  cudaGetSymbolAddress((void**)&gq, g_q);
  float* gk;  cudaGetSymbolAddress((void**)&gk, g_k);
  float* gv;  cudaGetSymbolAddress((void**)&gv, g_v);
  float* gom; cudaGetSymbolAddress((void**)&gom, g_omix);

  static const int smem_uw = (3 * 64 * LD + 64 * 136) * 4;
  static const int smem_rc = 4 * 64 * LD * 4;
  static const int smem_ol = 5 * 64 * LD * 4;
  static const int smem_at = 4 * 64 * LD * 4;
  cudaFuncSetAttribute(uw_kernel, cudaFuncAttributeMaxDynamicSharedMemorySize, smem_uw);
  cudaFuncSetAttribute(recur_kernel, cudaFuncAttributeMaxDynamicSharedMemorySize, smem_rc);
  cudaFuncSetAttribute(olin_kernel, cudaFuncAttributeMaxDynamicSharedMemorySize, smem_ol);
  cudaFuncSetAttribute(attn_kernel, cudaFuncAttributeMaxDynamicSharedMemorySize, smem_at);

  sgemm_kernel<<<dim3(16, 16), 256>>>(hidden, Wq, gq, 2048, 2048);
  sgemm_kernel<<<dim3(4, 16), 256>>>(hidden, Wk, gk, 512, 2048);
  sgemm_kernel<<<dim3(4, 16), 256>>>(hidden, Wv, gv, 512, 2048);
  prep_kernel<<<10240, 256>>>();
  uw_kernel<<<256, 256, smem_uw>>>();
  recur_kernel<<<16, 256, smem_rc>>>();
  olin_kernel<<<1024, 256, smem_ol>>>();
  attn_kernel<<<dim3(16, 32, 2), 256, smem_at>>>(attn_out, write_attn);
  sgemm_kernel<<<dim3(16, 16), 256>>>(gom, Wo, out, 2048, 2048);
}

// round 6
// speedup vs baseline: 1.7365x; 1.7365x over previous
#include <cuda_runtime.h>
#include <cuda_bf16.h>
#include <cstdint>
#include <math.h>

#define LD 68

// ---------------- scratch ----------------
__device__ float g_q[2048 * 2048];
__device__ float g_k[2048 * 512];
__device__ float g_v[2048 * 512];
__device__ float g_ql[2 * 32 * 1024 * 64];
__device__ float g_kl[2 * 8 * 1024 * 64];
__device__ float g_gl[2 * 8 * 1024 * 64];
__device__ float g_vh[2 * 8 * 1024 * 64];
__device__ float g_uw[2 * 8 * 16 * 64 * 128];
__device__ float g_up[2 * 8 * 16 * 64 * 64];
__device__ float g_Spre[2 * 8 * 16 * 64 * 64];
__device__ float g_olin[2048 * 2048];
__device__ float g_omix[2048 * 2048];

__device__ __nv_bfloat16 g_Ah[2048 * 2048];
__device__ __nv_bfloat16 g_Al[2048 * 2048];
__device__ __nv_bfloat16 g_Wqh[2048 * 2048];
__device__ __nv_bfloat16 g_Wql[2048 * 2048];
__device__ __nv_bfloat16 g_Wkh[512 * 2048];
__device__ __nv_bfloat16 g_Wkl[512 * 2048];
__device__ __nv_bfloat16 g_Wvh[512 * 2048];
__device__ __nv_bfloat16 g_Wvl[512 * 2048];
__device__ __nv_bfloat16 g_Woh[2048 * 2048];
__device__ __nv_bfloat16 g_Wol[2048 * 2048];

__device__ __forceinline__ uint32_t smem_u32(const void* p) {
  uint32_t a;
  asm("{ .reg .u64 t; cvta.to.shared.u64 t, %1; cvt.u32.u64 %0, t; }" : "=r"(a) : "l"(p));
  return a;
}

#define LDSM4(r, addr)                                                        \
  asm volatile("ldmatrix.sync.aligned.m8n8.x4.shared.b16 {%0,%1,%2,%3}, [%4];"\
               : "=r"((r)[0]), "=r"((r)[1]), "=r"((r)[2]), "=r"((r)[3])       \
               : "r"(addr))

#define MMA16816(c, a, b)                                                     \
  asm volatile(                                                               \
      "mma.sync.aligned.m16n8k16.row.col.f32.bf16.bf16.f32 "                  \
      "{%0,%1,%2,%3},{%4,%5,%6,%7},{%8,%9},{%0,%1,%2,%3};"                    \
      : "+f"((c)[0]), "+f"((c)[1]), "+f"((c)[2]), "+f"((c)[3])                \
      : "r"((a)[0]), "r"((a)[1]), "r"((a)[2]), "r"((a)[3]),                   \
        "r"((b)[0]), "r"((b)[1]))

// ---------------- split kernels ----------------
__global__ __launch_bounds__(256) void split_kernel(
    const float* __restrict__ x, __nv_bfloat16* __restrict__ hi,
    __nv_bfloat16* __restrict__ lo, int n4) {
  int i = blockIdx.x * 256 + threadIdx.x;
  if (i >= n4) return;
  float4 v = ((const float4*)x)[i];
  __nv_bfloat16 h0 = __float2bfloat16(v.x), h1 = __float2bfloat16(v.y);
  __nv_bfloat16 h2 = __float2bfloat16(v.z), h3 = __float2bfloat16(v.w);
  __nv_bfloat16 l0 = __float2bfloat16(v.x - __bfloat162float(h0));
  __nv_bfloat16 l1 = __float2bfloat16(v.y - __bfloat162float(h1));
  __nv_bfloat16 l2 = __float2bfloat16(v.z - __bfloat162float(h2));
  __nv_bfloat16 l3 = __float2bfloat16(v.w - __bfloat162float(h3));
  __nv_bfloat162* H = (__nv_bfloat162*)hi;
  __nv_bfloat162* L = (__nv_bfloat162*)lo;
  H[2 * i] = __halves2bfloat162(h0, h1);
  H[2 * i + 1] = __halves2bfloat162(h2, h3);
  L[2 * i] = __halves2bfloat162(l0, l1);
  L[2 * i + 1] = __halves2bfloat162(l2, l3);
}

// W [K x N] -> hiT/loT [N x K]
__global__ __launch_bounds__(256) void splitT_kernel(
    const float* __restrict__ W, __nv_bfloat16* __restrict__ hiT,
    __nv_bfloat16* __restrict__ loT, int K, int N) {
  __shared__ float t[32][33];
  int nx = blockIdx.x * 32, ky = blockIdx.y * 32;
  int tx = threadIdx.x & 31, ty = threadIdx.x >> 5;
  for (int j = ty; j < 32; j += 8)
    t[j][tx] = W[(size_t)(ky + j) * N + nx + tx];
  __syncthreads();
  for (int j = ty; j < 32; j += 8) {
    float v = t[tx][j];
    __nv_bfloat16 h = __float2bfloat16(v);
    __nv_bfloat16 l = __float2bfloat16(v - __bfloat162float(h));
    size_t o = (size_t)(nx + j) * K + ky + tx;
    hiT[o] = h;
    loT[o] = l;
  }
}

// ---------------- HMMA bf16 split GEMM: C[MxN] = A @ B^T ----------------
// A (Ah,Al): [M x K] bf16 row-major.  B (Bh,Bl): [N x K] bf16 row-major.
// D = Ah Bh^T + Ah Bl^T + Al Bh^T with fp32 accumulators.
__global__ __launch_bounds__(256) void hmma_gemm(
    const __nv_bfloat16* __restrict__ Ah, const __nv_bfloat16* __restrict__ Al,
    const __nv_bfloat16* __restrict__ Bh, const __nv_bfloat16* __restrict__ Bl,
    float* __restrict__ C, int N, int K) {
  extern __shared__ __align__(128) char smem[];
  const uint32_t sb = smem_u32(smem);
  const int tid = threadIdx.x, wid = tid >> 5, lane = tid & 31;
  const int wy = wid & 3, wx = wid >> 2;  // 4 warps in m, 2 in n
  const int m0 = blockIdx.y * 128, n0 = blockIdx.x * 128;
  const int nchunks = K >> 5;  // K-chunks of 32
  // stage buffers 40960B each: Ah@0 Al@10240 Bh@20480 Bl@30720, row stride 80B
  const __nv_bfloat16* srcs[4] = {Ah, Al, Bh, Bl};

  float acc[2][8][4];
#pragma unroll
  for (int mt = 0; mt < 2; mt++)
#pragma unroll
    for (int nt = 0; nt < 8; nt++)
#pragma unroll
      for (int e = 0; e < 4; e++) acc[mt][nt][e] = 0.f;

  // prologue: chunks 0 and 1
#pragma unroll
  for (int pc = 0; pc < 2; pc++) {
    uint32_t base = sb + pc * 40960;
#pragma unroll
    for (int it = 0; it < 8; it++) {
      int idx = it * 256 + tid;
      int mat = idx >> 9;
      int r = (idx >> 2) & 127;
      int seg = idx & 3;
      int grow = (mat < 2 ? m0 : n0) + r;
      const char* g = (const char*)(srcs[mat] + (size_t)grow * K + pc * 32) + seg * 16;
      uint32_t sa = base + mat * 10240 + r * 80 + seg * 16;
      asm volatile("cp.async.cg.shared.global [%0], [%1], 16;" :: "r"(sa), "l"(g));
    }
    asm volatile("cp.async.commit_group;");
  }

  for (int kc = 0; kc < nchunks; kc++) {
    if (kc == nchunks - 1)
      asm volatile("cp.async.wait_group 0;");
    else
      asm volatile("cp.async.wait_group 1;");
    __syncthreads();
    const uint32_t base = sb + (kc & 1) * 40960;
#pragma unroll
    for (int ks = 0; ks < 2; ks++) {
      uint32_t ah[2][4], al[2][4], bh[8][2], bl[8][2];
#pragma unroll
      for (int mt = 0; mt < 2; mt++) {
        int row = wy * 32 + mt * 16 + (lane & 15);
        uint32_t off = row * 80 + (ks * 16 + (lane >> 4) * 8) * 2;
        LDSM4(ah[mt], base + off);
        LDSM4(al[mt], base + 10240 + off);
      }
#pragma unroll
      for (int np = 0; np < 4; np++) {
        int j = lane >> 3;
        int row = wx * 64 + np * 16 + (j >> 1) * 8 + (lane & 7);
        uint32_t off = row * 80 + (ks * 16 + (j & 1) * 8) * 2;
        LDSM4(bh[2 * np], base + 20480 + off);
        LDSM4(bl[2 * np], base + 30720 + off);
      }
#pragma unroll
      for (int mt = 0; mt < 2; mt++)
#pragma unroll
        for (int nt = 0; nt < 8; nt++) {
          MMA16816(acc[mt][nt], ah[mt], bh[nt]);
          MMA16816(acc[mt][nt], ah[mt], bl[nt]);
          MMA16816(acc[mt][nt], al[mt], bh[nt]);
        }
    }
    __syncthreads();
    if (kc + 2 < nchunks) {
      uint32_t lbase = sb + (kc & 1) * 40960;
#pragma unroll
      for (int it = 0; it < 8; it++) {
        int idx = it * 256 + tid;
        int mat = idx >> 9;
        int r = (idx >> 2) & 127;
        int seg = idx & 3;
        int grow = (mat < 2 ? m0 : n0) + r;
        const char* g =
            (const char*)(srcs[mat] + (size_t)grow * K + (kc + 2) * 32) + seg * 16;
        uint32_t sa = lbase + mat * 10240 + r * 80 + seg * 16;
        asm volatile("cp.async.cg.shared.global [%0], [%1], 16;" :: "r"(sa), "l"(g));
      }
      asm volatile("cp.async.commit_group;");
    }
  }

#pragma unroll
  for (int mt = 0; mt < 2; mt++)
#pragma unroll
    for (int nt = 0; nt < 8; nt++) {
      int row = m0 + wy * 32 + mt * 16 + (lane >> 2);
      int col = n0 + wx * 64 + nt * 8 + (lane & 3) * 2;
      *(float2*)&C[(size_t)row * N + col] =
          make_float2(acc[mt][nt][0], acc[mt][nt][1]);
      *(float2*)&C[(size_t)(row + 8) * N + col] =
          make_float2(acc[mt][nt][2], acc[mt][nt][3]);
    }
}

// ---------------- feature maps ----------------
__global__ __launch_bounds__(256) void prep_kernel() {
  int gw = (blockIdx.x * 256 + threadIdx.x) >> 5;
  int lane = threadIdx.x & 31;
  if (gw < 65536) {
    int token = gw >> 5, h = gw & 31;
    const float* src = g_q + (size_t)token * 2048 + h * 64;
    float x0 = src[lane], x1 = src[lane + 32];
    float mx = fmaxf(x0, x1);
#pragma unroll
    for (int o = 16; o > 0; o >>= 1) mx = fmaxf(mx, __shfl_xor_sync(0xffffffffu, mx, o));
    float e0 = __expf(x0 - mx), e1 = __expf(x1 - mx);
    float s = e0 + e1;
#pragma unroll
    for (int o = 16; o > 0; o >>= 1) s += __shfl_xor_sync(0xffffffffu, s, o);
    float inv = 1.f / s;
    int b = token >> 10, n = token & 1023;
    float* dst = g_ql + ((size_t)((b * 32 + h) * 1024 + n)) * 64;
    dst[lane] = e0 * inv;
    dst[lane + 32] = e1 * inv;
  } else {
    int j = gw - 65536;
    int token = j >> 3, hk = j & 7;
    const float* ks = g_k + (size_t)token * 512 + hk * 64;
    const float* vs = g_v + (size_t)token * 512 + hk * 64;
    float x0 = ks[lane], x1 = ks[lane + 32];
    float mx = fmaxf(x0, x1);
#pragma unroll
    for (int o = 16; o > 0; o >>= 1) mx = fmaxf(mx, __shfl_xor_sync(0xffffffffu, mx, o));
    float e0 = __expf(x0 - mx), e1 = __expf(x1 - mx);
    float s = e0 + e1;
#pragma unroll
    for (int o = 16; o > 0; o >>= 1) s += __shfl_xor_sync(0xffffffffu, s, o);
    float inv = 1.f / s;
    int b = token >> 10, n = token & 1023;
    size_t base = ((size_t)((b * 8 + hk) * 1024 + n)) * 64;
    g_kl[base + lane] = e0 * inv;
    g_kl[base + lane + 32] = e1 * inv;
    g_gl[base + lane] = (fminf(x0, 0.f) - log1pf(__expf(-fabsf(x0)))) * 0.0625f;
    g_gl[base + lane + 32] = (fminf(x1, 0.f) - log1pf(__expf(-fabsf(x1)))) * 0.0625f;
    g_vh[base + lane] = vs[lane];
    g_vh[base + lane + 32] = vs[lane + 32];
  }
}

// ---------------- per-chunk u,w ----------------
__global__ __launch_bounds__(256) void uw_kernel() {
  extern __shared__ float sm_uw[];
  float* kcT = sm_uw;
  float* kb = kcT + 64 * LD;
  float* L = kb + 64 * LD;
  float* uw = L + 64 * LD;
  const int bx = blockIdx.x;
  const int g = bx >> 4, ch = bx & 15;
  const int tid = threadIdx.x, tx = tid & 15, ty = tid >> 4;
  size_t base = ((size_t)g * 1024 + ch * 64) * 64;
  for (int idx = tid; idx < 4096; idx += 256) {
    int r = idx >> 6, c = idx & 63;
    float kv = g_kl[base + idx];
    float gv = g_gl[base + idx];
    float vv = g_vh[base + idx];
    kcT[c * LD + r] = kv;
    float kbv = kv * gv;
    kb[r * LD + c] = kbv;
    uw[r * 136 + c] = vv * gv;
    uw[r * 136 + 64 + c] = kbv;
  }
  __syncthreads();
  float acc[4][4] = {};
#pragma unroll 8
  for (int d = 0; d < 64; d++) {
    float a[4];
#pragma unroll
    for (int i = 0; i < 4; i++) a[i] = kb[(ty * 4 + i) * LD + d];
    float4 b4 = *(const float4*)&kcT[d * LD + tx * 4];
#pragma unroll
    for (int i = 0; i < 4; i++) {
      acc[i][0] += a[i] * b4.x; acc[i][1] += a[i] * b4.y;
      acc[i][2] += a[i] * b4.z; acc[i][3] += a[i] * b4.w;
    }
  }
#pragma unroll
  for (int i = 0; i < 4; i++)
#pragma unroll
    for (int j = 0; j < 4; j++) {
      int ii = ty * 4 + i, jj = tx * 4 + j;
      L[ii * LD + jj] = (ii > jj) ? acc[i][j] : 0.f;
    }
  __syncthreads();
  for (int i = 1; i < 64; i++) {
    if (tid < 128) {
      float s = 0.f;
      const float* Li = L + i * LD;
      for (int j = 0; j < i; j++) s += Li[j] * uw[j * 136 + tid];
      uw[i * 136 + tid] -= s;
    }
    __syncthreads();
  }
  float* dst = g_uw + (size_t)bx * 8192;
  for (int idx = tid; idx < 8192; idx += 256)
    dst[idx] = uw[(idx >> 7) * 136 + (idx & 127)];
}

// ---------------- state recurrence ----------------
__global__ __launch_bounds__(256) void recur_kernel() {
  extern __shared__ float sm_rc[];
  float* S = sm_rc;
  float* w = S + 64 * LD;
  float* up = w + 64 * LD;
  float* kc = up + 64 * LD;
  const int g = blockIdx.x;
  const int tid = threadIdx.x, tx = tid & 15, ty = tid >> 4;
  for (int idx = tid; idx < 4096; idx += 256) S[(idx >> 6) * LD + (idx & 63)] = 0.f;
  __syncthreads();
  for (int ch = 0; ch < 16; ch++) {
    size_t bi = (size_t)(g * 16 + ch);
    const float* uwp = g_uw + bi * 8192;
    size_t kbase = ((size_t)g * 1024 + ch * 64) * 64;
    for (int idx = tid; idx < 4096; idx += 256) {
      int r = idx >> 6, c = idx & 63;
      w[r * LD + c] = uwp[r * 128 + 64 + c];
      kc[r * LD + c] = g_kl[kbase + idx];
      g_Spre[bi * 4096 + idx] = S[r * LD + c];
    }
    __syncthreads();
    float acc[4][4] = {};
#pragma unroll 8
    for (int d = 0; d < 64; d++) {
      float a[4];
#pragma unroll
      for (int i = 0; i < 4; i++) a[i] = w[(ty * 4 + i) * LD + d];
      float4 b4 = *(const float4*)&S[d * LD + tx * 4];
#pragma unroll
      for (int i = 0; i < 4; i++) {
        acc[i][0] += a[i] * b4.x; acc[i][1] += a[i] * b4.y;
        acc[i][2] += a[i] * b4.z; acc[i][3] += a[i] * b4.w;
      }
    }
#pragma unroll
    for (int i = 0; i < 4; i++)
#pragma unroll
      for (int j = 0; j < 4; j++) {
        int r = ty * 4 + i, c = tx * 4 + j;
        float upv = uwp[r * 128 + c] - acc[i][j];
        up[r * LD + c] = upv;
        g_up[bi * 4096 + r * 64 + c] = upv;
      }
    __syncthreads();
    float acc2[4][4] = {};
#pragma unroll 8
    for (int c0 = 0; c0 < 64; c0++) {
      float a[4];
#pragma unroll
      for (int i = 0; i < 4; i++) a[i] = kc[c0 * LD + ty * 4 + i];
      float4 b4 = *(const float4*)&up[c0 * LD + tx * 4];
#pragma unroll
      for (int i = 0; i < 4; i++) {
        acc2[i][0] += a[i] * b4.x; acc2[i][1] += a[i] * b4.y;
        acc2[i][2] += a[i] * b4.z; acc2[i][3] += a[i] * b4.w;
      }
    }
#pragma unroll
    for (int i = 0; i < 4; i++)
#pragma unroll
      for (int j = 0; j < 4; j++)
        S[(ty * 4 + i) * LD + tx * 4 + j] += acc2[i][j];
    __syncthreads();
  }
}

// ---------------- linear-branch output ----------------
__global__ __launch_bounds__(256) void olin_kernel() {
  extern __shared__ float sm_ol[];
  float* QT = sm_ol;
  float* KT = QT + 64 * LD;
  float* S = KT + 64 * LD;
  float* UP = S + 64 * LD;
  float* AT = UP + 64 * LD;
  const int bx = blockIdx.x;
  const int bh = bx >> 4, ch = bx & 15;
  const int b = bh >> 5, h = bh & 31;
  const int g = b * 8 + (h >> 2);
  const int tid = threadIdx.x, tx = tid & 15, ty = tid >> 4;
  size_t qbase = ((size_t)bh * 1024 + ch * 64) * 64;
  size_t kbase = ((size_t)g * 1024 + ch * 64) * 64;
  size_t sbase = (size_t)(g * 16 + ch) * 4096;
  for (int idx = tid; idx < 4096; idx += 256) {
    int r = idx >> 6, c = idx & 63;
    QT[c * LD + r] = g_ql[qbase + idx];
    KT[c * LD + r] = g_kl[kbase + idx];
    S[r * LD + c] = g_Spre[sbase + idx];
    UP[r * LD + c] = g_up[sbase + idx];
  }
  __syncthreads();
  float acc[4][4] = {};
#pragma unroll 8
  for (int d = 0; d < 64; d++) {
    float a[4];
#pragma unroll
    for (int i = 0; i < 4; i++) a[i] = QT[d * LD + ty * 4 + i];
    float4 b4 = *(const float4*)&KT[d * LD + tx * 4];
#pragma unroll
    for (int i = 0; i < 4; i++) {
      acc[i][0] += a[i] * b4.x; acc[i][1] += a[i] * b4.y;
      acc[i][2] += a[i] * b4.z; acc[i][3] += a[i] * b4.w;
    }
  }
#pragma unroll
  for (int i = 0; i < 4; i++)
#pragma unroll
    for (int j = 0; j < 4; j++) {
      int ii = ty * 4 + i, jj = tx * 4 + j;
      AT[ii * LD + jj] = (jj <= ii) ? acc[i][j] : 0.f;
    }
  __syncthreads();
  float o[4][4] = {};
#pragma unroll 8
  for (int d = 0; d < 64; d++) {
    float a[4];
#pragma unroll
    for (int i = 0; i < 4; i++) a[i] = QT[d * LD + ty * 4 + i];
    float4 b4 = *(const float4*)&S[d * LD + tx * 4];
#pragma unroll
    for (int i = 0; i < 4; i++) {
      o[i][0] += a[i] * b4.x; o[i][1] += a[i] * b4.y;
      o[i][2] += a[i] * b4.z; o[i][3] += a[i] * b4.w;
    }
  }
#pragma unroll 8
  for (int j0 = 0; j0 < 64; j0++) {
    float a[4];
#pragma unroll
    for (int i = 0; i < 4; i++) a[i] = AT[(ty * 4 + i) * LD + j0];
    float4 b4 = *(const float4*)&UP[j0 * LD + tx * 4];
#pragma unroll
    for (int i = 0; i < 4; i++) {
      o[i][0] += a[i] * b4.x; o[i][1] += a[i] * b4.y;
      o[i][2] += a[i] * b4.z; o[i][3] += a[i] * b4.w;
    }
  }
#pragma unroll
  for (int i = 0; i < 4; i++) {
    size_t ob = ((size_t)(b * 1024 + ch * 64 + ty * 4 + i)) * 2048 + h * 64 + tx * 4;
    *(float4*)&g_olin[ob] = make_float4(o[i][0], o[i][1], o[i][2], o[i][3]);
  }
}

// ---------------- base attention ----------------
__global__ __launch_bounds__(256) void attn_kernel(float* __restrict__ attn_out, int write_attn) {
  extern __shared__ float sm_at[];
  float* QT = sm_at;
  float* KT = QT + 64 * LD;
  float* VS = KT + 64 * LD;
  float* PS = VS + 64 * LD;
  const int qt = blockIdx.x, h = blockIdx.y, b = blockIdx.z;
  const int hk = h >> 2;
  const int tid = threadIdx.x, tx = tid & 15, ty = tid >> 4;
  const int r0 = ty * 4;
  for (int idx = tid; idx < 4096; idx += 256) {
    int r = idx >> 6, d = idx & 63;
    QT[d * LD + r] = g_q[((size_t)(b * 1024 + qt * 64 + r)) * 2048 + h * 64 + d] * 0.125f;
  }
  float m[4], l[4], o[4][4];
#pragma unroll
  for (int i = 0; i < 4; i++) {
    m[i] = -1e30f; l[i] = 0.f;
#pragma unroll
    for (int j = 0; j < 4; j++) o[i][j] = 0.f;
  }
  for (int kt = 0; kt <= qt; kt++) {
    __syncthreads();
    for (int idx = tid; idx < 4096; idx += 256) {
      int r = idx >> 6, d = idx & 63;
      KT[d * LD + r] = g_k[((size_t)(b * 1024 + kt * 64 + r)) * 512 + hk * 64 + d];
    }
    __syncthreads();
    float s[4][4] = {};
#pragma unroll 8
    for (int d = 0; d < 64; d++) {
      float a[4];
#pragma unroll
      for (int i = 0; i < 4; i++) a[i] = QT[d * LD + r0 + i];
      float4 b4 = *(const float4*)&KT[d * LD + tx * 4];
#pragma unroll
      for (int i = 0; i < 4; i++) {
        s[i][0] += a[i] * b4.x; s[i][1] += a[i] * b4.y;
        s[i][2] += a[i] * b4.z; s[i][3] += a[i] * b4.w;
      }
    }
    bool diag = (kt == qt);
#pragma unroll
    for (int i = 0; i < 4; i++) {
      if (diag) {
#pragma unroll
        for (int j = 0; j < 4; j++)
          if (tx * 4 + j > r0 + i) s[i][j] = -1e30f;
      }
      float tmax = fmaxf(fmaxf(s[i][0], s[i][1]), fmaxf(s[i][2], s[i][3]));
#pragma unroll
      for (int off = 8; off > 0; off >>= 1)
        tmax = fmaxf(tmax, __shfl_xor_sync(0xffffffffu, tmax, off));
      float mn = fmaxf(m[i], tmax);
      float ps = __expf(s[i][0] - mn) + __expf(s[i][1] - mn) +
                 __expf(s[i][2] - mn) + __expf(s[i][3] - mn);
#pragma unroll
      for (int off = 8; off > 0; off >>= 1) ps += __shfl_xor_sync(0xffffffffu, ps, off);
      l[i] = l[i] * __expf(m[i] - mn) + ps;
      m[i] = mn;
    }
  }
  float invl[4];
#pragma unroll
  for (int i = 0; i < 4; i++) invl[i] = 1.f / l[i];
  const size_t arow0 = (size_t)(b * 32 + h) * 1024 + (size_t)qt * 64;
  for (int kt = 0; kt < 16; kt++) {
    if (kt <= qt) {
      __syncthreads();
      for (int idx = tid; idx < 4096; idx += 256) {
        int r = idx >> 6, d = idx & 63;
        size_t src = ((size_t)(b * 1024 + kt * 64 + r)) * 512 + hk * 64 + d;
        KT[d * LD + r] = g_k[src];
        VS[r * LD + d] = g_v[src];
      }
      __syncthreads();
      float s[4][4] = {};
#pragma unroll 8
      for (int d = 0; d < 64; d++) {
        float a[4];
#pragma unroll
        for (int i = 0; i < 4; i++) a[i] = QT[d * LD + r0 + i];
        float4 b4 = *(const float4*)&KT[d * LD + tx * 4];
#pragma unroll
        for (int i = 0; i < 4; i++) {
          s[i][0] += a[i] * b4.x; s[i][1] += a[i] * b4.y;
          s[i][2] += a[i] * b4.z; s[i][3] += a[i] * b4.w;
        }
      }
      bool diag = (kt == qt);
#pragma unroll
      for (int i = 0; i < 4; i++) {
        float p[4];
#pragma unroll
        for (int j = 0; j < 4; j++) {
          bool valid = !diag || (tx * 4 + j <= r0 + i);
          p[j] = valid ? __expf(s[i][j] - m[i]) * invl[i] : 0.f;
          PS[(r0 + i) * LD + tx * 4 + j] = p[j];
        }
        if (write_attn) {
          *(float4*)&attn_out[(arow0 + r0 + i) * 1024 + kt * 64 + tx * 4] =
              make_float4(p[0], p[1], p[2], p[3]);
        }
      }
      __syncthreads();
#pragma unroll 8
      for (int j0 = 0; j0 < 64; j0++) {
        float a[4];
#pragma unroll
        for (int i = 0; i < 4; i++) a[i] = PS[(r0 + i) * LD + j0];
        float4 b4 = *(const float4*)&VS[j0 * LD + tx * 4];
#pragma unroll
        for (int i = 0; i < 4; i++) {
          o[i][0] += a[i] * b4.x; o[i][1] += a[i] * b4.y;
          o[i][2] += a[i] * b4.z; o[i][3] += a[i] * b4.w;
        }
      }
    } else if (write_attn) {
#pragma unroll
      for (int i = 0; i < 4; i++)
        *(float4*)&attn_out[(arow0 + r0 + i) * 1024 + kt * 64 + tx * 4] =
            make_float4(0.f, 0.f, 0.f, 0.f);
    }
  }
#pragma unroll
  for (int i = 0; i < 4; i++) {
    size_t ob = ((size_t)(b * 1024 + qt * 64 + r0 + i)) * 2048 + h * 64 + tx * 4;
    float4 ol = *(const float4*)&g_olin[ob];
    *(float4*)&g_omix[ob] = make_float4(0.5f * (ol.x + o[i][0]), 0.5f * (ol.y + o[i][1]),
                                        0.5f * (ol.z + o[i][2]), 0.5f * (ol.w + o[i][3]));
  }
}

extern "C" void kernel_launch(void* const* d_in, const int* in_sizes, int n_in,
                              void* d_out, int out_size) {
  const float* hidden = (const float*)d_in[0];
  const float* Wq = (const float*)d_in[1];
  const float* Wk = (const float*)d_in[2];
  const float* Wv = (const float*)d_in[3];
  const float* Wo = (const float*)d_in[4];
  float* out = (float*)d_out;
  float* attn_out = out + 4194304;
  int write_attn = (out_size >= 71303168) ? 1 : 0;

  float* gq;  cudaGetSymbolAddress((void**)&gq, g_q);
  float* gk;  cudaGetSymbolAddress((void**)&gk, g_k);
  float* gv;  cudaGetSymbolAddress((void**)&gv, g_v);
  float* gom; cudaGetSymbolAddress((void**)&gom, g_omix);
  __nv_bfloat16 *gAh, *gAl, *gWqh, *gWql, *gWkh, *gWkl, *gWvh, *gWvl, *gWoh, *gWol;
  cudaGetSymbolAddress((void**)&gAh, g_Ah);
  cudaGetSymbolAddress((void**)&gAl, g_Al);
  cudaGetSymbolAddress((void**)&gWqh, g_Wqh);
  cudaGetSymbolAddress((void**)&gWql, g_Wql);
  cudaGetSymbolAddress((void**)&gWkh, g_Wkh);
  cudaGetSymbolAddress((void**)&gWkl, g_Wkl);
  cudaGetSymbolAddress((void**)&gWvh, g_Wvh);
  cudaGetSymbolAddress((void**)&gWvl, g_Wvl);
  cudaGetSymbolAddress((void**)&gWoh, g_Woh);
  cudaGetSymbolAddress((void**)&gWol, g_Wol);

  static const int smem_uw = (3 * 64 * LD + 64 * 136) * 4;
  static const int smem_rc = 4 * 64 * LD * 4;
  static const int smem_ol = 5 * 64 * LD * 4;
  static const int smem_at = 4 * 64 * LD * 4;
  static const int smem_g = 2 * 40960;
  cudaFuncSetAttribute(uw_kernel, cudaFuncAttributeMaxDynamicSharedMemorySize, smem_uw);
  cudaFuncSetAttribute(recur_kernel, cudaFuncAttributeMaxDynamicSharedMemorySize, smem_rc);
  cudaFuncSetAttribute(olin_kernel, cudaFuncAttributeMaxDynamicSharedMemorySize, smem_ol);
  cudaFuncSetAttribute(attn_kernel, cudaFuncAttributeMaxDynamicSharedMemorySize, smem_at);
  cudaFuncSetAttribute(hmma_gemm, cudaFuncAttributeMaxDynamicSharedMemorySize, smem_g);

  split_kernel<<<4096, 256>>>(hidden, gAh, gAl, 1048576);
  splitT_kernel<<<dim3(64, 64), 256>>>(Wq, gWqh, gWql, 2048, 2048);
  splitT_kernel<<<dim3(16, 64), 256>>>(Wk, gWkh, gWkl, 2048, 512);
  splitT_kernel<<<dim3(16, 64), 256>>>(Wv, gWvh, gWvl, 2048, 512);
  splitT_kernel<<<dim3(64, 64), 256>>>(Wo, gWoh, gWol, 2048, 2048);

  hmma_gemm<<<dim3(16, 16), 256, smem_g>>>(gAh, gAl, gWqh, gWql, gq, 2048, 2048);
  hmma_gemm<<<dim3(4, 16), 256, smem_g>>>(gAh, gAl, gWkh, gWkl, gk, 512, 2048);
  hmma_gemm<<<dim3(4, 16), 256, smem_g>>>(gAh, gAl, gWvh, gWvl, gv, 512, 2048);

  prep_kernel<<<10240, 256>>>();
  uw_kernel<<<256, 256, smem_uw>>>();
  recur_kernel<<<16, 256, smem_rc>>>();
  olin_kernel<<<1024, 256, smem_ol>>>();
  attn_kernel<<<dim3(16, 32, 2), 256, smem_at>>>(attn_out, write_attn);

  split_kernel<<<4096, 256>>>(gom, gAh, gAl, 1048576);
  hmma_gemm<<<dim3(16, 16), 256, smem_g>>>(gAh, gAl, gWoh, gWol, out, 2048, 2048);
}

// round 9
// speedup vs baseline: 2.3797x; 1.3704x over previous
#include <cuda_runtime.h>
#include <cuda_bf16.h>
#include <cstdint>
#include <math.h>

#define LD 68

// ---------------- scratch ----------------
__device__ float g_q[2048 * 2048];
__device__ float g_k[2048 * 512];
__device__ float g_v[2048 * 512];
__device__ float g_ql[2 * 32 * 1024 * 64];
__device__ float g_kl[2 * 8 * 1024 * 64];
__device__ float g_gl[2 * 8 * 1024 * 64];
__device__ float g_vh[2 * 8 * 1024 * 64];
__device__ float g_uw[2 * 8 * 16 * 64 * 128];
__device__ float g_up[2 * 8 * 16 * 64 * 64];
__device__ float g_Spre[2 * 8 * 16 * 64 * 64];
__device__ float g_olin[2048 * 2048];
__device__ float g_omix[2048 * 2048];

__device__ __nv_bfloat16 g_Ah[2048 * 2048];
__device__ __nv_bfloat16 g_Al[2048 * 2048];
__device__ __nv_bfloat16 g_Wqh[2048 * 2048];
__device__ __nv_bfloat16 g_Wql[2048 * 2048];
__device__ __nv_bfloat16 g_Wkh[512 * 2048];
__device__ __nv_bfloat16 g_Wkl[512 * 2048];
__device__ __nv_bfloat16 g_Wvh[512 * 2048];
__device__ __nv_bfloat16 g_Wvl[512 * 2048];
__device__ __nv_bfloat16 g_Woh[2048 * 2048];
__device__ __nv_bfloat16 g_Wol[2048 * 2048];

// bf16 split q/k/v for HMMA attention (head-major)
__device__ __nv_bfloat16 g_qsh[2 * 32 * 1024 * 64];
__device__ __nv_bfloat16 g_qsl[2 * 32 * 1024 * 64];
__device__ __nv_bfloat16 g_ksh[2 * 8 * 1024 * 64];
__device__ __nv_bfloat16 g_ksl[2 * 8 * 1024 * 64];
__device__ __nv_bfloat16 g_vsh[2 * 8 * 1024 * 64];
__device__ __nv_bfloat16 g_vsl[2 * 8 * 1024 * 64];

__device__ __forceinline__ uint32_t smem_u32(const void* p) {
  uint32_t a;
  asm("{ .reg .u64 t; cvta.to.shared.u64 t, %1; cvt.u32.u64 %0, t; }" : "=r"(a) : "l"(p));
  return a;
}

#define LDSM4(r, addr)                                                        \
  asm volatile("ldmatrix.sync.aligned.m8n8.x4.shared.b16 {%0,%1,%2,%3}, [%4];"\
               : "=r"((r)[0]), "=r"((r)[1]), "=r"((r)[2]), "=r"((r)[3])       \
               : "r"(addr))

#define LDSM4T(r, addr)                                                       \
  asm volatile(                                                               \
      "ldmatrix.sync.aligned.m8n8.x4.trans.shared.b16 {%0,%1,%2,%3}, [%4];"   \
      : "=r"((r)[0]), "=r"((r)[1]), "=r"((r)[2]), "=r"((r)[3])                \
      : "r"(addr))

#define MMA16816(c, a, b)                                                     \
  asm volatile(                                                               \
      "mma.sync.aligned.m16n8k16.row.col.f32.bf16.bf16.f32 "                  \
      "{%0,%1,%2,%3},{%4,%5,%6,%7},{%8,%9},{%0,%1,%2,%3};"                    \
      : "+f"((c)[0]), "+f"((c)[1]), "+f"((c)[2]), "+f"((c)[3])                \
      : "r"((a)[0]), "r"((a)[1]), "r"((a)[2]), "r"((a)[3]),                   \
        "r"((b)[0]), "r"((b)[1]))

#define CPA16(dst, src)                                                       \
  asm volatile("cp.async.cg.shared.global [%0], [%1], 16;" :: "r"(dst), "l"(src))
#define CPCOMMIT() asm volatile("cp.async.commit_group;")
#define CPWAITALL() asm volatile("cp.async.wait_group 0;")

// ---------------- split kernels ----------------
__global__ __launch_bounds__(256) void split_kernel(
    const float* __restrict__ x, __nv_bfloat16* __restrict__ hi,
    __nv_bfloat16* __restrict__ lo, int n4) {
  int i = blockIdx.x * 256 + threadIdx.x;
  if (i >= n4) return;
  float4 v = ((const float4*)x)[i];
  __nv_bfloat16 h0 = __float2bfloat16(v.x), h1 = __float2bfloat16(v.y);
  __nv_bfloat16 h2 = __float2bfloat16(v.z), h3 = __float2bfloat16(v.w);
  __nv_bfloat16 l0 = __float2bfloat16(v.x - __bfloat162float(h0));
  __nv_bfloat16 l1 = __float2bfloat16(v.y - __bfloat162float(h1));
  __nv_bfloat16 l2 = __float2bfloat16(v.z - __bfloat162float(h2));
  __nv_bfloat16 l3 = __float2bfloat16(v.w - __bfloat162float(h3));
  __nv_bfloat162* H = (__nv_bfloat162*)hi;
  __nv_bfloat162* L = (__nv_bfloat162*)lo;
  H[2 * i] = __halves2bfloat162(h0, h1);
  H[2 * i + 1] = __halves2bfloat162(h2, h3);
  L[2 * i] = __halves2bfloat162(l0, l1);
  L[2 * i + 1] = __halves2bfloat162(l2, l3);
}

__global__ __launch_bounds__(256) void splitT_kernel(
    const float* __restrict__ W, __nv_bfloat16* __restrict__ hiT,
    __nv_bfloat16* __restrict__ loT, int K, int N) {
  __shared__ float t[32][33];
  int nx = blockIdx.x * 32, ky = blockIdx.y * 32;
  int tx = threadIdx.x & 31, ty = threadIdx.x >> 5;
  for (int j = ty; j < 32; j += 8)
    t[j][tx] = W[(size_t)(ky + j) * N + nx + tx];
  __syncthreads();
  for (int j = ty; j < 32; j += 8) {
    float v = t[tx][j];
    __nv_bfloat16 h = __float2bfloat16(v);
    __nv_bfloat16 l = __float2bfloat16(v - __bfloat162float(h));
    size_t o = (size_t)(nx + j) * K + ky + tx;
    hiT[o] = h;
    loT[o] = l;
  }
}

// ---------------- HMMA bf16 split GEMM ----------------
__global__ __launch_bounds__(256) void hmma_gemm(
    const __nv_bfloat16* __restrict__ Ah, const __nv_bfloat16* __restrict__ Al,
    const __nv_bfloat16* __restrict__ Bh, const __nv_bfloat16* __restrict__ Bl,
    float* __restrict__ C, int N, int K) {
  extern __shared__ __align__(128) char smem[];
  const uint32_t sb = smem_u32(smem);
  const int tid = threadIdx.x, wid = tid >> 5, lane = tid & 31;
  const int wy = wid & 3, wx = wid >> 2;
  const int m0 = blockIdx.y * 128, n0 = blockIdx.x * 128;
  const int nchunks = K >> 5;
  const __nv_bfloat16* srcs[4] = {Ah, Al, Bh, Bl};

  float acc[2][8][4];
#pragma unroll
  for (int mt = 0; mt < 2; mt++)
#pragma unroll
    for (int nt = 0; nt < 8; nt++)
#pragma unroll
      for (int e = 0; e < 4; e++) acc[mt][nt][e] = 0.f;

#pragma unroll
  for (int pc = 0; pc < 2; pc++) {
    uint32_t base = sb + pc * 40960;
#pragma unroll
    for (int it = 0; it < 8; it++) {
      int idx = it * 256 + tid;
      int mat = idx >> 9;
      int r = (idx >> 2) & 127;
      int seg = idx & 3;
      int grow = (mat < 2 ? m0 : n0) + r;
      const char* g = (const char*)(srcs[mat] + (size_t)grow * K + pc * 32) + seg * 16;
      CPA16(base + mat * 10240 + r * 80 + seg * 16, g);
    }
    CPCOMMIT();
  }

  for (int kc = 0; kc < nchunks; kc++) {
    if (kc == nchunks - 1)
      asm volatile("cp.async.wait_group 0;");
    else
      asm volatile("cp.async.wait_group 1;");
    __syncthreads();
    const uint32_t base = sb + (kc & 1) * 40960;
#pragma unroll
    for (int ks = 0; ks < 2; ks++) {
      uint32_t ah[2][4], al[2][4], bh[8][2], bl[8][2];
#pragma unroll
      for (int mt = 0; mt < 2; mt++) {
        int row = wy * 32 + mt * 16 + (lane & 15);
        uint32_t off = row * 80 + (ks * 16 + (lane >> 4) * 8) * 2;
        LDSM4(ah[mt], base + off);
        LDSM4(al[mt], base + 10240 + off);
      }
#pragma unroll
      for (int np = 0; np < 4; np++) {
        int j = lane >> 3;
        int row = wx * 64 + np * 16 + (j >> 1) * 8 + (lane & 7);
        uint32_t off = row * 80 + (ks * 16 + (j & 1) * 8) * 2;
        LDSM4(bh[2 * np], base + 20480 + off);
        LDSM4(bl[2 * np], base + 30720 + off);
      }
#pragma unroll
      for (int mt = 0; mt < 2; mt++)
#pragma unroll
        for (int nt = 0; nt < 8; nt++) {
          MMA16816(acc[mt][nt], ah[mt], bh[nt]);
          MMA16816(acc[mt][nt], ah[mt], bl[nt]);
          MMA16816(acc[mt][nt], al[mt], bh[nt]);
        }
    }
    __syncthreads();
    if (kc + 2 < nchunks) {
      uint32_t lbase = sb + (kc & 1) * 40960;
#pragma unroll
      for (int it = 0; it < 8; it++) {
        int idx = it * 256 + tid;
        int mat = idx >> 9;
        int r = (idx >> 2) & 127;
        int seg = idx & 3;
        int grow = (mat < 2 ? m0 : n0) + r;
        const char* g =
            (const char*)(srcs[mat] + (size_t)grow * K + (kc + 2) * 32) + seg * 16;
        CPA16(lbase + mat * 10240 + r * 80 + seg * 16, g);
      }
      CPCOMMIT();
    }
  }

#pragma unroll
  for (int mt = 0; mt < 2; mt++)
#pragma unroll
    for (int nt = 0; nt < 8; nt++) {
      int row = m0 + wy * 32 + mt * 16 + (lane >> 2);
      int col = n0 + wx * 64 + nt * 8 + (lane & 3) * 2;
      *(float2*)&C[(size_t)row * N + col] =
          make_float2(acc[mt][nt][0], acc[mt][nt][1]);
      *(float2*)&C[(size_t)(row + 8) * N + col] =
          make_float2(acc[mt][nt][2], acc[mt][nt][3]);
    }
}

// ---------------- feature maps + bf16 splits ----------------
__global__ __launch_bounds__(256) void prep_kernel() {
  int gw = (blockIdx.x * 256 + threadIdx.x) >> 5;
  int lane = threadIdx.x & 31;
  if (gw < 65536) {
    int token = gw >> 5, h = gw & 31;
    const float* src = g_q + (size_t)token * 2048 + h * 64;
    float x0 = src[lane], x1 = src[lane + 32];
    float mx = fmaxf(x0, x1);
#pragma unroll
    for (int o = 16; o > 0; o >>= 1) mx = fmaxf(mx, __shfl_xor_sync(0xffffffffu, mx, o));
    float e0 = __expf(x0 - mx), e1 = __expf(x1 - mx);
    float s = e0 + e1;
#pragma unroll
    for (int o = 16; o > 0; o >>= 1) s += __shfl_xor_sync(0xffffffffu, s, o);
    float inv = 1.f / s;
    int b = token >> 10, n = token & 1023;
    size_t hb = ((size_t)((b * 32 + h) * 1024 + n)) * 64;
    g_ql[hb + lane] = e0 * inv;
    g_ql[hb + lane + 32] = e1 * inv;
    // scaled bf16 split for base attention
    float s0 = x0 * 0.125f, s1 = x1 * 0.125f;
    __nv_bfloat16 h0 = __float2bfloat16(s0), h1 = __float2bfloat16(s1);
    g_qsh[hb + lane] = h0;
    g_qsh[hb + lane + 32] = h1;
    g_qsl[hb + lane] = __float2bfloat16(s0 - __bfloat162float(h0));
    g_qsl[hb + lane + 32] = __float2bfloat16(s1 - __bfloat162float(h1));
  } else {
    int j = gw - 65536;
    int token = j >> 3, hk = j & 7;
    const float* ks = g_k + (size_t)token * 512 + hk * 64;
    const float* vs = g_v + (size_t)token * 512 + hk * 64;
    float x0 = ks[lane], x1 = ks[lane + 32];
    float v0 = vs[lane], v1 = vs[lane + 32];
    float mx = fmaxf(x0, x1);
#pragma unroll
    for (int o = 16; o > 0; o >>= 1) mx = fmaxf(mx, __shfl_xor_sync(0xffffffffu, mx, o));
    float e0 = __expf(x0 - mx), e1 = __expf(x1 - mx);
    float s = e0 + e1;
#pragma unroll
    for (int o = 16; o > 0; o >>= 1) s += __shfl_xor_sync(0xffffffffu, s, o);
    float inv = 1.f / s;
    int b = token >> 10, n = token & 1023;
    size_t base = ((size_t)((b * 8 + hk) * 1024 + n)) * 64;
    g_kl[base + lane] = e0 * inv;
    g_kl[base + lane + 32] = e1 * inv;
    g_gl[base + lane] = (fminf(x0, 0.f) - log1pf(__expf(-fabsf(x0)))) * 0.0625f;
    g_gl[base + lane + 32] = (fminf(x1, 0.f) - log1pf(__expf(-fabsf(x1)))) * 0.0625f;
    g_vh[base + lane] = v0;
    g_vh[base + lane + 32] = v1;
    __nv_bfloat16 kh0 = __float2bfloat16(x0), kh1 = __float2bfloat16(x1);
    g_ksh[base + lane] = kh0;
    g_ksh[base + lane + 32] = kh1;
    g_ksl[base + lane] = __float2bfloat16(x0 - __bfloat162float(kh0));
    g_ksl[base + lane + 32] = __float2bfloat16(x1 - __bfloat162float(kh1));
    __nv_bfloat16 vh0 = __float2bfloat16(v0), vh1 = __float2bfloat16(v1);
    g_vsh[base + lane] = vh0;
    g_vsh[base + lane + 32] = vh1;
    g_vsl[base + lane] = __float2bfloat16(v0 - __bfloat162float(vh0));
    g_vsl[base + lane + 32] = __float2bfloat16(v1 - __bfloat162float(vh1));
  }
}

// ---------------- per-chunk u,w ----------------
__global__ __launch_bounds__(256) void uw_kernel() {
  extern __shared__ float sm_uw[];
  float* kcT = sm_uw;
  float* kb = kcT + 64 * LD;
  float* L = kb + 64 * LD;
  float* uw = L + 64 * LD;
  const int bx = blockIdx.x;
  const int g = bx >> 4, ch = bx & 15;
  const int tid = threadIdx.x, tx = tid & 15, ty = tid >> 4;
  size_t base = ((size_t)g * 1024 + ch * 64) * 64;
  for (int idx = tid; idx < 4096; idx += 256) {
    int r = idx >> 6, c = idx & 63;
    float kv = g_kl[base + idx];
    float gv = g_gl[base + idx];
    float vv = g_vh[base + idx];
    kcT[c * LD + r] = kv;
    float kbv = kv * gv;
    kb[r * LD + c] = kbv;
    uw[r * 136 + c] = vv * gv;
    uw[r * 136 + 64 + c] = kbv;
  }
  __syncthreads();
  float acc[4][4] = {};
#pragma unroll 8
  for (int d = 0; d < 64; d++) {
    float a[4];
#pragma unroll
    for (int i = 0; i < 4; i++) a[i] = kb[(ty * 4 + i) * LD + d];
    float4 b4 = *(const float4*)&kcT[d * LD + tx * 4];
#pragma unroll
    for (int i = 0; i < 4; i++) {
      acc[i][0] += a[i] * b4.x; acc[i][1] += a[i] * b4.y;
      acc[i][2] += a[i] * b4.z; acc[i][3] += a[i] * b4.w;
    }
  }
#pragma unroll
  for (int i = 0; i < 4; i++)
#pragma unroll
    for (int j = 0; j < 4; j++) {
      int ii = ty * 4 + i, jj = tx * 4 + j;
      L[ii * LD + jj] = (ii > jj) ? acc[i][j] : 0.f;
    }
  __syncthreads();
  for (int i = 1; i < 64; i++) {
    if (tid < 128) {
      float s = 0.f;
      const float* Li = L + i * LD;
      for (int j = 0; j < i; j++) s += Li[j] * uw[j * 136 + tid];
      uw[i * 136 + tid] -= s;
    }
    __syncthreads();
  }
  float* dst = g_uw + (size_t)bx * 8192;
  for (int idx = tid; idx < 8192; idx += 256)
    dst[idx] = uw[(idx >> 7) * 136 + (idx & 127)];
}

// ---------------- state recurrence, e-split x4 (64 blocks) ----------------
__global__ __launch_bounds__(256) void recur_kernel() {
  __shared__ float S[64 * 17];
  __shared__ float up[64 * 17];
  __shared__ float w[64 * 68];
  __shared__ float kc[64 * 68];
  const int g = blockIdx.x >> 2, es = (blockIdx.x & 3) * 16;
  const int tid = threadIdx.x;
  const int col = tid & 15, rq = tid >> 4;
  for (int i = tid; i < 1024; i += 256) S[(i >> 4) * 17 + (i & 15)] = 0.f;
  __syncthreads();
  for (int ch = 0; ch < 16; ch++) {
    size_t bi = (size_t)(g * 16 + ch);
    const float* uwp = g_uw + bi * 8192;
    size_t kbase = ((size_t)g * 1024 + ch * 64) * 64;
    for (int idx = tid; idx < 4096; idx += 256) {
      int r = idx >> 6, c = idx & 63;
      w[r * 68 + c] = uwp[r * 128 + 64 + c];
      kc[r * 68 + c] = g_kl[kbase + idx];
    }
    for (int i = tid; i < 1024; i += 256) {
      int r = i >> 4, c = i & 15;
      g_Spre[bi * 4096 + r * 64 + es + c] = S[r * 17 + c];
    }
    __syncthreads();
    float a[4] = {};
#pragma unroll 8
    for (int d = 0; d < 64; d++) {
      float sv = S[d * 17 + col];
#pragma unroll
      for (int i = 0; i < 4; i++) a[i] += w[(rq * 4 + i) * 68 + d] * sv;
    }
    float upv[4];
#pragma unroll
    for (int i = 0; i < 4; i++) {
      upv[i] = uwp[(rq * 4 + i) * 128 + es + col] - a[i];
      up[(rq * 4 + i) * 17 + col] = upv[i];
      g_up[bi * 4096 + (rq * 4 + i) * 64 + es + col] = upv[i];
    }
    __syncthreads();
    float b4[4] = {};
#pragma unroll 8
    for (int c = 0; c < 64; c++) {
      float uv = up[c * 17 + col];
#pragma unroll
      for (int i = 0; i < 4; i++) b4[i] += kc[c * 68 + rq * 4 + i] * uv;
    }
#pragma unroll
    for (int i = 0; i < 4; i++) S[(rq * 4 + i) * 17 + col] += b4[i];
    __syncthreads();
  }
}

// ---------------- linear-branch output ----------------
__global__ __launch_bounds__(256) void olin_kernel() {
  extern __shared__ float sm_ol[];
  float* QT = sm_ol;
  float* KT = QT + 64 * LD;
  float* S = KT + 64 * LD;
  float* UP = S + 64 * LD;
  float* AT = UP + 64 * LD;
  const int bx = blockIdx.x;
  const int bh = bx >> 4, ch = bx & 15;
  const int b = bh >> 5, h = bh & 31;
  const int g = b * 8 + (h >> 2);
  const int tid = threadIdx.x, tx = tid & 15, ty = tid >> 4;
  size_t qbase = ((size_t)bh * 1024 + ch * 64) * 64;
  size_t kbase = ((size_t)g * 1024 + ch * 64) * 64;
  size_t sbase = (size_t)(g * 16 + ch) * 4096;
  for (int idx = tid; idx < 4096; idx += 256) {
    int r = idx >> 6, c = idx & 63;
    QT[c * LD + r] = g_ql[qbase + idx];
    KT[c * LD + r] = g_kl[kbase + idx];
    S[r * LD + c] = g_Spre[sbase + idx];
    UP[r * LD + c] = g_up[sbase + idx];
  }
  __syncthreads();
  float acc[4][4] = {};
#pragma unroll 8
  for (int d = 0; d < 64; d++) {
    float a[4];
#pragma unroll
    for (int i = 0; i < 4; i++) a[i] = QT[d * LD + ty * 4 + i];
    float4 b4 = *(const float4*)&KT[d * LD + tx * 4];
#pragma unroll
    for (int i = 0; i < 4; i++) {
      acc[i][0] += a[i] * b4.x; acc[i][1] += a[i] * b4.y;
      acc[i][2] += a[i] * b4.z; acc[i][3] += a[i] * b4.w;
    }
  }
#pragma unroll
  for (int i = 0; i < 4; i++)
#pragma unroll
    for (int j = 0; j < 4; j++) {
      int ii = ty * 4 + i, jj = tx * 4 + j;
      AT[ii * LD + jj] = (jj <= ii) ? acc[i][j] : 0.f;
    }
  __syncthreads();
  float o[4][4] = {};
#pragma unroll 8
  for (int d = 0; d < 64; d++) {
    float a[4];
#pragma unroll
    for (int i = 0; i < 4; i++) a[i] = QT[d * LD + ty * 4 + i];
    float4 b4 = *(const float4*)&S[d * LD + tx * 4];
#pragma unroll
    for (int i = 0; i < 4; i++) {
      o[i][0] += a[i] * b4.x; o[i][1] += a[i] * b4.y;
      o[i][2] += a[i] * b4.z; o[i][3] += a[i] * b4.w;
    }
  }
#pragma unroll 8
  for (int j0 = 0; j0 < 64; j0++) {
    float a[4];
#pragma unroll
    for (int i = 0; i < 4; i++) a[i] = AT[(ty * 4 + i) * LD + j0];
    float4 b4 = *(const float4*)&UP[j0 * LD + tx * 4];
#pragma unroll
    for (int i = 0; i < 4; i++) {
      o[i][0] += a[i] * b4.x; o[i][1] += a[i] * b4.y;
      o[i][2] += a[i] * b4.z; o[i][3] += a[i] * b4.w;
    }
  }
#pragma unroll
  for (int i = 0; i < 4; i++) {
    size_t ob = ((size_t)(b * 1024 + ch * 64 + ty * 4 + i)) * 2048 + h * 64 + tx * 4;
    *(float4*)&g_olin[ob] = make_float4(o[i][0], o[i][1], o[i][2], o[i][3]);
  }
}

// ---------------- HMMA base attention ----------------
// block: (qt, h, b); 8 warps as 4(m-rows of q tile) x 2(n-cols)
__global__ __launch_bounds__(256) void attn_hmma(float* __restrict__ attn_out,
                                                 int write_attn) {
  extern __shared__ __align__(128) char sm[];
  const uint32_t sb = smem_u32(sm);
  const int qt = blockIdx.x, h = blockIdx.y, b = blockIdx.z;
  const int hk = h >> 2;
  const int tid = threadIdx.x, wid = tid >> 5, lane = tid & 31;
  const int wy = wid & 3, wx = wid >> 2;
  const uint32_t QH = 0, QL = 9216, KHo = 18432, KLo = 27648, VHo = 36864,
                 VLo = 46080, PHo = 55296, PLo = 64512, RED = 73728;
  float* REDm = (float*)(sm + RED);
  float* REDs = (float*)(sm + RED + 512);
  const size_t qbase = ((size_t)((b * 32 + h) * 1024) + (size_t)qt * 64) * 64;
  const size_t kvb = ((size_t)((b * 8 + hk) * 1024)) * 64;

  // load Q hi/lo
  {
#pragma unroll
    for (int i = 0; i < 4; i++) {
      int idx = i * 256 + tid;
      int mat = idx >> 9;
      int ri = idx & 511;
      int row = ri >> 3, seg = ri & 7;
      const char* g =
          (const char*)((mat ? g_qsl : g_qsh) + qbase + (size_t)row * 64 + seg * 8);
      CPA16(sb + (mat ? QL : QH) + row * 144 + seg * 16, g);
    }
    CPCOMMIT();
  }

  float m[2] = {-1e30f, -1e30f}, l[2] = {0.f, 0.f};
  const int r0i = wy * 16 + (lane >> 2);

  // ---- pass 1: m, l ----
  for (int kt = 0; kt <= qt; kt++) {
    __syncthreads();
#pragma unroll
    for (int i = 0; i < 4; i++) {
      int idx = i * 256 + tid;
      int mat = idx >> 9;
      int ri = idx & 511;
      int row = ri >> 3, seg = ri & 7;
      const char* g = (const char*)((mat ? g_ksl : g_ksh) + kvb +
                                    (size_t)(kt * 64 + row) * 64 + seg * 8);
      CPA16(sb + (mat ? KLo : KHo) + row * 144 + seg * 16, g);
    }
    CPCOMMIT();
    CPWAITALL();
    __syncthreads();
    float s[4][4] = {};
#pragma unroll
    for (int ks = 0; ks < 4; ks++) {
      uint32_t qhf[4], qlf[4], kf[4][2], klf[4][2];
      uint32_t qoff = (wy * 16 + (lane & 15)) * 144 + ks * 32 + (lane >> 4) * 16;
      LDSM4(qhf, sb + QH + qoff);
      LDSM4(qlf, sb + QL + qoff);
#pragma unroll
      for (int np = 0; np < 2; np++) {
        int j = lane >> 3;
        uint32_t off =
            (wx * 32 + np * 16 + (j >> 1) * 8 + (lane & 7)) * 144 + ks * 32 + (j & 1) * 16;
        LDSM4(kf[2 * np], sb + KHo + off);
        LDSM4(klf[2 * np], sb + KLo + off);
      }
#pragma unroll
      for (int sub = 0; sub < 4; sub++) {
        MMA16816(s[sub], qhf, kf[sub]);
        MMA16816(s[sub], qhf, klf[sub]);
        MMA16816(s[sub], qlf, kf[sub]);
      }
    }
    if (kt == qt) {
      int gr = qt * 64 + r0i;
#pragma unroll
      for (int sub = 0; sub < 4; sub++) {
        int gc = kt * 64 + wx * 32 + sub * 8 + (lane & 3) * 2;
        if (gc > gr) s[sub][0] = -1e30f;
        if (gc + 1 > gr) s[sub][1] = -1e30f;
        if (gc > gr + 8) s[sub][2] = -1e30f;
        if (gc + 1 > gr + 8) s[sub][3] = -1e30f;
      }
    }
    float mx0 = -1e30f, mx1 = -1e30f;
#pragma unroll
    for (int sub = 0; sub < 4; sub++) {
      mx0 = fmaxf(mx0, fmaxf(s[sub][0], s[sub][1]));
      mx1 = fmaxf(mx1, fmaxf(s[sub][2], s[sub][3]));
    }
    mx0 = fmaxf(mx0, __shfl_xor_sync(0xffffffffu, mx0, 1));
    mx0 = fmaxf(mx0, __shfl_xor_sync(0xffffffffu, mx0, 2));
    mx1 = fmaxf(mx1, __shfl_xor_sync(0xffffffffu, mx1, 1));
    mx1 = fmaxf(mx1, __shfl_xor_sync(0xffffffffu, mx1, 2));
    if ((lane & 3) == 0) {
      REDm[r0i * 2 + wx] = mx0;
      REDm[(r0i + 8) * 2 + wx] = mx1;
    }
    __syncthreads();
    float nm0 = fmaxf(m[0], fmaxf(REDm[r0i * 2], REDm[r0i * 2 + 1]));
    float nm1 = fmaxf(m[1], fmaxf(REDm[(r0i + 8) * 2], REDm[(r0i + 8) * 2 + 1]));
    float ps0 = 0.f, ps1 = 0.f;
#pragma unroll
    for (int sub = 0; sub < 4; sub++) {
      ps0 += __expf(s[sub][0] - nm0) + __expf(s[sub][1] - nm0);
      ps1 += __expf(s[sub][2] - nm1) + __expf(s[sub][3] - nm1);
    }
    ps0 += __shfl_xor_sync(0xffffffffu, ps0, 1);
    ps0 += __shfl_xor_sync(0xffffffffu, ps0, 2);
    ps1 += __shfl_xor_sync(0xffffffffu, ps1, 1);
    ps1 += __shfl_xor_sync(0xffffffffu, ps1, 2);
    if ((lane & 3) == 0) {
      REDs[r0i * 2 + wx] = ps0;
      REDs[(r0i + 8) * 2 + wx] = ps1;
    }
    __syncthreads();
    l[0] = l[0] * __expf(m[0] - nm0) + REDs[r0i * 2] + REDs[r0i * 2 + 1];
    l[1] = l[1] * __expf(m[1] - nm1) + REDs[(r0i + 8) * 2] + REDs[(r0i + 8) * 2 + 1];
    m[0] = nm0;
    m[1] = nm1;
  }

  float invl0 = 1.f / l[0], invl1 = 1.f / l[1];
  float o[4][4] = {};
  const size_t arow0 = (size_t)(b * 32 + h) * 1024 + (size_t)qt * 64;

  // ---- pass 2: p, attn_out, PV ----
  for (int kt = 0; kt < 16; kt++) {
    if (kt <= qt) {
      __syncthreads();
#pragma unroll
      for (int i = 0; i < 8; i++) {
        int idx = i * 256 + tid;
        int mat = idx >> 9;  // 0:KH 1:KL 2:VH 3:VL
        int ri = idx & 511;
        int row = ri >> 3, seg = ri & 7;
        const __nv_bfloat16* srcp = (mat == 0)   ? g_ksh
                                    : (mat == 1) ? g_ksl
                                    : (mat == 2) ? g_vsh
                                                 : g_vsl;
        const char* g =
            (const char*)(srcp + kvb + (size_t)(kt * 64 + row) * 64 + seg * 8);
        CPA16(sb + KHo + mat * 9216 + row * 144 + seg * 16, g);
      }
      CPCOMMIT();
      CPWAITALL();
      __syncthreads();
      float s[4][4] = {};
#pragma unroll
      for (int ks = 0; ks < 4; ks++) {
        uint32_t qhf[4], qlf[4], kf[4][2], klf[4][2];
        uint32_t qoff = (wy * 16 + (lane & 15)) * 144 + ks * 32 + (lane >> 4) * 16;
        LDSM4(qhf, sb + QH + qoff);
        LDSM4(qlf, sb + QL + qoff);
#pragma unroll
        for (int np = 0; np < 2; np++) {
          int j = lane >> 3;
          uint32_t off = (wx * 32 + np * 16 + (j >> 1) * 8 + (lane & 7)) * 144 +
                         ks * 32 + (j & 1) * 16;
          LDSM4(kf[2 * np], sb + KHo + off);
          LDSM4(klf[2 * np], sb + KLo + off);
        }
#pragma unroll
        for (int sub = 0; sub < 4; sub++) {
          MMA16816(s[sub], qhf, kf[sub]);
          MMA16816(s[sub], qhf, klf[sub]);
          MMA16816(s[sub], qlf, kf[sub]);
        }
      }
      if (kt == qt) {
        int gr = qt * 64 + r0i;
#pragma unroll
        for (int sub = 0; sub < 4; sub++) {
          int gc = kt * 64 + wx * 32 + sub * 8 + (lane & 3) * 2;
          if (gc > gr) s[sub][0] = -1e30f;
          if (gc + 1 > gr) s[sub][1] = -1e30f;
          if (gc > gr + 8) s[sub][2] = -1e30f;
          if (gc + 1 > gr + 8) s[sub][3] = -1e30f;
        }
      }
#pragma unroll
      for (int sub = 0; sub < 4; sub++) {
        float p0 = __expf(s[sub][0] - m[0]) * invl0;
        float p1 = __expf(s[sub][1] - m[0]) * invl0;
        float p2 = __expf(s[sub][2] - m[1]) * invl1;
        float p3 = __expf(s[sub][3] - m[1]) * invl1;
        int cl = wx * 32 + sub * 8 + (lane & 3) * 2;
        if (write_attn) {
          int col = kt * 64 + cl;
          *(float2*)&attn_out[(arow0 + r0i) * 1024 + col] = make_float2(p0, p1);
          *(float2*)&attn_out[(arow0 + r0i + 8) * 1024 + col] = make_float2(p2, p3);
        }
        __nv_bfloat16 h0 = __float2bfloat16(p0), h1 = __float2bfloat16(p1);
        __nv_bfloat16 h2 = __float2bfloat16(p2), h3 = __float2bfloat16(p3);
        *(__nv_bfloat162*)(sm + PHo + r0i * 144 + cl * 2) = __halves2bfloat162(h0, h1);
        *(__nv_bfloat162*)(sm + PHo + (r0i + 8) * 144 + cl * 2) =
            __halves2bfloat162(h2, h3);
        *(__nv_bfloat162*)(sm + PLo + r0i * 144 + cl * 2) = __halves2bfloat162(
            __float2bfloat16(p0 - __bfloat162float(h0)),
            __float2bfloat16(p1 - __bfloat162float(h1)));
        *(__nv_bfloat162*)(sm + PLo + (r0i + 8) * 144 + cl * 2) = __halves2bfloat162(
            __float2bfloat16(p2 - __bfloat162float(h2)),
            __float2bfloat16(p3 - __bfloat162float(h3)));
      }
      __syncthreads();
#pragma unroll
      for (int ks = 0; ks < 4; ks++) {
        uint32_t pf[4], plf[4], vf[4][2], vlf[4][2];
        uint32_t poff = (wy * 16 + (lane & 15)) * 144 + ks * 32 + (lane >> 4) * 16;
        LDSM4(pf, sb + PHo + poff);
        LDSM4(plf, sb + PLo + poff);
#pragma unroll
        for (int np = 0; np < 2; np++) {
          int g2 = lane >> 3;
          uint32_t off = (ks * 16 + (g2 & 1) * 8 + (lane & 7)) * 144 +
                         (wx * 32 + np * 16) * 2 + (g2 >> 1) * 16;
          LDSM4T(vf[2 * np], sb + VHo + off);
          LDSM4T(vlf[2 * np], sb + VLo + off);
        }
#pragma unroll
        for (int sub = 0; sub < 4; sub++) {
          MMA16816(o[sub], pf, vf[sub]);
          MMA16816(o[sub], plf, vf[sub]);
          MMA16816(o[sub], pf, vlf[sub]);
        }
      }
    } else if (write_attn) {
#pragma unroll
      for (int i = 0; i < 4; i++) {
        int idx = i * 256 + tid;
        int row = idx >> 4, c4 = (idx & 15) * 4;
        *(float4*)&attn_out[(arow0 + row) * 1024 + kt * 64 + c4] =
            make_float4(0.f, 0.f, 0.f, 0.f);
      }
    }
  }

  // epilogue: fuse 0.5*(olin + obase)
#pragma unroll
  for (int sub = 0; sub < 4; sub++) {
    int gr = qt * 64 + r0i;
    int col = wx * 32 + sub * 8 + (lane & 3) * 2;
    size_t ob = ((size_t)(b * 1024 + gr)) * 2048 + h * 64 + col;
    float2 ol = *(const float2*)&g_olin[ob];
    *(float2*)&g_omix[ob] =
        make_float2(0.5f * (ol.x + o[sub][0]), 0.5f * (ol.y + o[sub][1]));
    size_t ob2 = ((size_t)(b * 1024 + gr + 8)) * 2048 + h * 64 + col;
    float2 ol2 = *(const float2*)&g_olin[ob2];
    *(float2*)&g_omix[ob2] =
        make_float2(0.5f * (ol2.x + o[sub][2]), 0.5f * (ol2.y + o[sub][3]));
  }
}

extern "C" void kernel_launch(void* const* d_in, const int* in_sizes, int n_in,
                              void* d_out, int out_size) {
  const float* hidden = (const float*)d_in[0];
  const float* Wq = (const float*)d_in[1];
  const float* Wk = (const float*)d_in[2];
  const float* Wv = (const float*)d_in[3];
  const float* Wo = (const float*)d_in[4];
  float* out = (float*)d_out;
  float* attn_out = out + 4194304;
  int write_attn = (out_size >= 71303168) ? 1 : 0;

  float* gq;  cudaGetSymbolAddress((void**)&gq, g_q);
  float* gk;  cudaGetSymbolAddress((void**)&gk, g_k);
  float* gv;  cudaGetSymbolAddress((void**)&gv, g_v);
  float* gom; cudaGetSymbolAddress((void**)&gom, g_omix);
  __nv_bfloat16 *gAh, *gAl, *gWqh, *gWql, *gWkh, *gWkl, *gWvh, *gWvl, *gWoh, *gWol;
  cudaGetSymbolAddress((void**)&gAh, g_Ah);
  cudaGetSymbolAddress((void**)&gAl, g_Al);
  cudaGetSymbolAddress((void**)&gWqh, g_Wqh);
  cudaGetSymbolAddress((void**)&gWql, g_Wql);
  cudaGetSymbolAddress((void**)&gWkh, g_Wkh);
  cudaGetSymbolAddress((void**)&gWkl, g_Wkl);
  cudaGetSymbolAddress((void**)&gWvh, g_Wvh);
  cudaGetSymbolAddress((void**)&gWvl, g_Wvl);
  cudaGetSymbolAddress((void**)&gWoh, g_Woh);
  cudaGetSymbolAddress((void**)&gWol, g_Wol);

  static const int smem_uw = (3 * 64 * LD + 64 * 136) * 4;
  static const int smem_ol = 5 * 64 * LD * 4;
  static const int smem_g = 2 * 40960;
  static const int smem_at = 74752;
  cudaFuncSetAttribute(uw_kernel, cudaFuncAttributeMaxDynamicSharedMemorySize, smem_uw);
  cudaFuncSetAttribute(olin_kernel, cudaFuncAttributeMaxDynamicSharedMemorySize, smem_ol);
  cudaFuncSetAttribute(hmma_gemm, cudaFuncAttributeMaxDynamicSharedMemorySize, smem_g);
  cudaFuncSetAttribute(attn_hmma, cudaFuncAttributeMaxDynamicSharedMemorySize, smem_at);

  split_kernel<<<4096, 256>>>(hidden, gAh, gAl, 1048576);
  splitT_kernel<<<dim3(64, 64), 256>>>(Wq, gWqh, gWql, 2048, 2048);
  splitT_kernel<<<dim3(16, 64), 256>>>(Wk, gWkh, gWkl, 2048, 512);
  splitT_kernel<<<dim3(16, 64), 256>>>(Wv, gWvh, gWvl, 2048, 512);
  splitT_kernel<<<dim3(64, 64), 256>>>(Wo, gWoh, gWol, 2048, 2048);

  hmma_gemm<<<dim3(16, 16), 256, smem_g>>>(gAh, gAl, gWqh, gWql, gq, 2048, 2048);
  hmma_gemm<<<dim3(4, 16), 256, smem_g>>>(gAh, gAl, gWkh, gWkl, gk, 512, 2048);
  hmma_gemm<<<dim3(4, 16), 256, smem_g>>>(gAh, gAl, gWvh, gWvl, gv, 512, 2048);

  prep_kernel<<<10240, 256>>>();
  uw_kernel<<<256, 256, smem_uw>>>();
  recur_kernel<<<64, 256>>>();
  olin_kernel<<<1024, 256, smem_ol>>>();
  attn_hmma<<<dim3(16, 32, 2), 256, smem_at>>>(attn_out, write_attn);

  split_kernel<<<4096, 256>>>(gom, gAh, gAl, 1048576);
  hmma_gemm<<<dim3(16, 16), 256, smem_g>>>(gAh, gAl, gWoh, gWol, out, 2048, 2048);
}